// round 10
// baseline (speedup 1.0000x reference)
#include <cuda_runtime.h>
#include <cuda_bf16.h>
#include <math.h>

#define BB 64
#define LL 1024
#define HH 64
#define H2 128
#define VV 32000
#define TOK 128
#define HPAD 68

// Scratch (device globals; no allocation allowed)
__device__ float  g_kall[BB * LL * HH];   // 16 MB
__device__ float4 g_meta[BB * LL];        // (rinv, 0.16*kk, dot(k_t,k_{t+1}), dot(k_t,k_{t+2}))
__device__ float  g_r2[BB * HH];

// ---------------------------------------------------------------------------
// Kernel 1: per-token front-end (measured-best r2 config: 512 thr, 128 tok)
// ---------------------------------------------------------------------------
__global__ void __launch_bounds__(512) k1_frontend(
        const int* __restrict__ seq, const float* __restrict__ embed,
        const float* __restrict__ W1, const float* __restrict__ b1,
        const float* __restrict__ W2, const float* __restrict__ b2,
        const float* __restrict__ gamma, const float* __restrict__ beta,
        const float* __restrict__ kpW) {
    extern __shared__ float sm[];
    float* h_sm  = sm;
    float* w1_sm = h_sm  + TOK * HPAD;
    float* u_sm  = w1_sm + HH * H2;
    float* w2_sm = u_sm  + TOK * H2;
    float* kp_sm = w2_sm + H2 * HH;
    float* b1s   = kp_sm + HH * HH;
    float* b2s   = b1s + H2;
    float* gsm   = b2s + HH;
    float* bsm   = gsm + HH;

    const int tid  = threadIdx.x;
    const int tok0 = blockIdx.x * TOK;

    for (int idx = tid; idx < HH * H2; idx += 512) w1_sm[idx] = W1[idx];
    for (int idx = tid; idx < H2 * HH; idx += 512) w2_sm[idx] = W2[idx];
    for (int idx = tid; idx < HH * HH; idx += 512) kp_sm[idx] = kpW[idx];
    if (tid < H2) b1s[tid] = b1[tid];
    if (tid < HH) { b2s[tid] = b2[tid]; gsm[tid] = gamma[tid]; bsm[tid] = beta[tid]; }

    #pragma unroll
    for (int k = 0; k < 16; k++) {
        int idx = tid + 512 * k;
        int t = idx >> 6, j = idx & 63;
        int row = seq[tok0 + t];
        h_sm[t * HPAD + j] = embed[row * HH + j];
    }
    __syncthreads();

    const int tt = tid >> 4;
    const int ct = tid & 15;

    // GEMM1
    {
        const int r0 = tt * 4, c0 = ct * 8;
        float acc[4][8];
        #pragma unroll
        for (int r = 0; r < 4; r++)
            #pragma unroll
            for (int c = 0; c < 8; c++) acc[r][c] = 0.f;
        #pragma unroll 2
        for (int j4 = 0; j4 < HH; j4 += 4) {
            float hv[4][4];
            #pragma unroll
            for (int r = 0; r < 4; r++)
                *(float4*)hv[r] = *(const float4*)&h_sm[(r0 + r) * HPAD + j4];
            #pragma unroll
            for (int jj = 0; jj < 4; jj++) {
                float4 wA = *(const float4*)&w1_sm[(j4 + jj) * H2 + c0];
                float4 wB = *(const float4*)&w1_sm[(j4 + jj) * H2 + c0 + 4];
                #pragma unroll
                for (int r = 0; r < 4; r++) {
                    float hvv = hv[r][jj];
                    acc[r][0] = fmaf(hvv, wA.x, acc[r][0]);
                    acc[r][1] = fmaf(hvv, wA.y, acc[r][1]);
                    acc[r][2] = fmaf(hvv, wA.z, acc[r][2]);
                    acc[r][3] = fmaf(hvv, wA.w, acc[r][3]);
                    acc[r][4] = fmaf(hvv, wB.x, acc[r][4]);
                    acc[r][5] = fmaf(hvv, wB.y, acc[r][5]);
                    acc[r][6] = fmaf(hvv, wB.z, acc[r][6]);
                    acc[r][7] = fmaf(hvv, wB.w, acc[r][7]);
                }
            }
        }
        #pragma unroll
        for (int r = 0; r < 4; r++)
            #pragma unroll
            for (int c = 0; c < 8; c++)
                u_sm[(r0 + r) * H2 + c0 + c] = fmaxf(acc[r][c] + b1s[c0 + c], 0.f);
    }
    __syncthreads();

    // GEMM2 + residual
    {
        const int r0 = tt * 4, c0 = ct * 4;
        float acc[4][4];
        #pragma unroll
        for (int r = 0; r < 4; r++)
            #pragma unroll
            for (int c = 0; c < 4; c++) acc[r][c] = 0.f;
        #pragma unroll 2
        for (int j4 = 0; j4 < H2; j4 += 4) {
            float uv[4][4];
            #pragma unroll
            for (int r = 0; r < 4; r++)
                *(float4*)uv[r] = *(const float4*)&u_sm[(r0 + r) * H2 + j4];
            #pragma unroll
            for (int jj = 0; jj < 4; jj++) {
                float4 w = *(const float4*)&w2_sm[(j4 + jj) * HH + c0];
                #pragma unroll
                for (int r = 0; r < 4; r++) {
                    float uvv = uv[r][jj];
                    acc[r][0] = fmaf(uvv, w.x, acc[r][0]);
                    acc[r][1] = fmaf(uvv, w.y, acc[r][1]);
                    acc[r][2] = fmaf(uvv, w.z, acc[r][2]);
                    acc[r][3] = fmaf(uvv, w.w, acc[r][3]);
                }
            }
        }
        #pragma unroll
        for (int r = 0; r < 4; r++)
            #pragma unroll
            for (int c = 0; c < 4; c++)
                h_sm[(r0 + r) * HPAD + c0 + c] += acc[r][c] + b2s[c0 + c];
    }
    __syncthreads();

    // LayerNorm per token
    if (tid < TOK) {
        float s = 0.f, ss = 0.f;
        #pragma unroll 8
        for (int j = 0; j < HH; j++) {
            float x = h_sm[tid * HPAD + j];
            s += x; ss += x * x;
        }
        float mu = s * (1.f / HH);
        float var = ss * (1.f / HH) - mu * mu;
        float rs = rsqrtf(var + 1e-5f);
        #pragma unroll 8
        for (int j = 0; j < HH; j++) {
            float x = h_sm[tid * HPAD + j];
            h_sm[tid * HPAD + j] = (x - mu) * rs * gsm[j] + bsm[j];
        }
    }
    __syncthreads();

    // GEMM3 -> g_kall
    {
        const int r0 = tt * 4, c0 = ct * 4;
        float acc[4][4];
        #pragma unroll
        for (int r = 0; r < 4; r++)
            #pragma unroll
            for (int c = 0; c < 4; c++) acc[r][c] = 0.f;
        #pragma unroll 2
        for (int j4 = 0; j4 < HH; j4 += 4) {
            float hv[4][4];
            #pragma unroll
            for (int r = 0; r < 4; r++)
                *(float4*)hv[r] = *(const float4*)&h_sm[(r0 + r) * HPAD + j4];
            #pragma unroll
            for (int jj = 0; jj < 4; jj++) {
                float4 w = *(const float4*)&kp_sm[(j4 + jj) * HH + c0];
                #pragma unroll
                for (int r = 0; r < 4; r++) {
                    float hvv = hv[r][jj];
                    acc[r][0] = fmaf(hvv, w.x, acc[r][0]);
                    acc[r][1] = fmaf(hvv, w.y, acc[r][1]);
                    acc[r][2] = fmaf(hvv, w.z, acc[r][2]);
                    acc[r][3] = fmaf(hvv, w.w, acc[r][3]);
                }
            }
        }
        #pragma unroll
        for (int r = 0; r < 4; r++)
            #pragma unroll
            for (int c = 0; c < 4; c++)
                g_kall[(tok0 + r0 + r) * HH + c0 + c] = acc[r][c];
    }
}

// ---------------------------------------------------------------------------
// Kernel 1b: per-(b,t) metadata: (rinv, 0.16*kk, dot(k_t,k_{t+1}), dot(k_t,k_{t+2}))
// ---------------------------------------------------------------------------
__global__ void k1b_meta() {
    const int g    = blockIdx.x * 8 + (threadIdx.x >> 5);
    const int lane = threadIdx.x & 31;
    const int b = g >> 10, t = g & 1023;
    if (t >= LL - 1) return;
    const float* kt = g_kall + (b * LL + t) * HH;
    float2 k0 = *(const float2*)&kt[lane * 2];
    float2 k1 = *(const float2*)&kt[HH + lane * 2];
    float2 k2v = make_float2(0.f, 0.f);
    if (t + 2 <= LL - 1) k2v = *(const float2*)&kt[2 * HH + lane * 2];
    float pkk = k0.x * k0.x + k0.y * k0.y;
    float pd1 = k0.x * k1.x + k0.y * k1.y;
    float pd2 = k0.x * k2v.x + k0.y * k2v.y;
    #pragma unroll
    for (int off = 16; off; off >>= 1) {
        pkk += __shfl_xor_sync(0xffffffffu, pkk, off);
        pd1 += __shfl_xor_sync(0xffffffffu, pd1, off);
        pd2 += __shfl_xor_sync(0xffffffffu, pd2, off);
    }
    if (lane == 0) {
        float rinv = 1.0f / fmaxf(sqrtf(pkk), 1e-12f);
        g_meta[b * LL + t] = make_float4(rinv, 0.16f * pkk, pd1, pd2);
    }
}

// ---------------------------------------------------------------------------
// Kernel 2: BATCH-PAIR interleaved scan. 64 threads process TWO independent
// batches (thread i owns M-row i of both). The two scans' instruction streams
// interleave, so one scan's shfl/LDS/gate latency hides under the other's
// FMAs. Lag-2 pipeline per batch, branchless update, one barrier per step.
// ---------------------------------------------------------------------------
__global__ void __launch_bounds__(64, 1) k2_scan(const float* __restrict__ rpW,
                                                 const float* __restrict__ rpb) {
    const int bp = blockIdx.x;           // batch pair
    const int i  = threadIdx.x;
    const int w  = i >> 5;
    __shared__ __align__(16) float kbuf[2][8][64];
    __shared__ float wsum[2][2][2];      // [u][parity][warp]
    __shared__ float rds[2][64];

    float M[2][64];
    #pragma unroll
    for (int u = 0; u < 2; u++)
        #pragma unroll
        for (int j = 0; j < 64; j++) M[u][j] = 0.f;

    const float*  kb[2] = { g_kall + (2 * bp + 0) * LL * HH,
                            g_kall + (2 * bp + 1) * LL * HH };
    const float4* mb[2] = { g_meta + (2 * bp + 0) * LL,
                            g_meta + (2 * bp + 1) * LL };

    // zero kbuf (slots 6,7 read at t=0,1 with gs2=0; must not be NaN)
    #pragma unroll
    for (int u = 0; u < 2; u++)
        #pragma unroll
        for (int sl = 0; sl < 8; sl++) kbuf[u][sl][i] = 0.f;

    float kc_cur[2], kc_nxt[2], xA[2], a[2], gs1[2], gs2[2], d1[2], d2[2], wpv[2];
    float4 mt[2];
    #pragma unroll
    for (int u = 0; u < 2; u++) {
        kc_cur[u] = kb[u][i];
        kc_nxt[u] = kb[u][HH + i];
        xA[u]     = kb[u][2 * HH + i];
        kbuf[u][0][i] = kc_cur[u];
        kbuf[u][1][i] = kc_nxt[u];
        mt[u] = mb[u][0];
        a[u] = 0.f; gs1[u] = 0.f; gs2[u] = 0.f;
        d1[u] = 0.f; d2[u] = 0.f; wpv[u] = 0.f;
    }
    __syncthreads();

    for (int t = 0; t < LL - 1; t++) {
        const int p = t & 1;
        float xB[2], s[2], err[2], perr[2];
        float4 mtn[2];

        #pragma unroll
        for (int u = 0; u < 2; u++) {
            xB[u]  = (t <= LL - 4) ? kb[u][(t + 3) * HH + i] : 0.f;
            mtn[u] = mb[u][t + 1];
            float vpk = fmaf(gs2[u], d2[u], fmaf(gs1[u], d1[u], a[u]));
            err[u] = fmaf(-mt[u].x, vpk, kc_cur[u]);   // k_i - rinv*vpk_i
            s[u]   = err[u] * mt[u].x;
            perr[u] = err[u] * err[u];
            kbuf[u][(t + 2) & 7][i] = xA[u];           // publish k^{t+2}
        }

        // two independent butterflies, interleaved level by level
        #pragma unroll
        for (int off = 16; off; off >>= 1) {
            perr[0] += __shfl_xor_sync(0xffffffffu, perr[0], off);
            perr[1] += __shfl_xor_sync(0xffffffffu, perr[1], off);
        }
        if ((i & 31) == 0) { wsum[0][p][w] = perr[0]; wsum[1][p][w] = perr[1]; }

        // branchless fused update + matvec for both batches
        #pragma unroll
        for (int u = 0; u < 2; u++) {
            const float* kp = kbuf[u][(t - 2) & 7];    // k^{t-2}
            const float* kn = kbuf[u][(t + 1) & 7];    // k^{t+1}
            float g = gs2[u];
            float v0 = 0.f, v1 = 0.f, v2 = 0.f, v3 = 0.f;
            #pragma unroll
            for (int j = 0; j < 64; j += 4) {
                float4 kp4 = *(const float4*)&kp[j];
                float4 kn4 = *(const float4*)&kn[j];
                M[u][j]     = fmaf(g, kp4.x, M[u][j]);     v0 = fmaf(M[u][j],     kn4.x, v0);
                M[u][j + 1] = fmaf(g, kp4.y, M[u][j + 1]); v1 = fmaf(M[u][j + 1], kn4.y, v1);
                M[u][j + 2] = fmaf(g, kp4.z, M[u][j + 2]); v2 = fmaf(M[u][j + 2], kn4.z, v2);
                M[u][j + 3] = fmaf(g, kp4.w, M[u][j + 3]); v3 = fmaf(M[u][j + 3], kn4.w, v3);
            }
            a[u] = (v0 + v1) + (v2 + v3);              // M_{t-2}@k^{t+1}
        }

        __syncthreads();
        #pragma unroll
        for (int u = 0; u < 2; u++) {
            float errsum = wsum[u][p][0] + wsum[u][p][1];
            int gate = errsum >= mt[u].y;              // ||err||^2 >= 0.16||k||^2
            gs2[u] = gs1[u];
            gs1[u] = gate ? s[u] : 0.f;
            d2[u] = wpv[u];        // D(t-1, t+1)
            d1[u] = mt[u].z;       // D(t,   t+1)
            wpv[u] = mt[u].w;
            mt[u] = mtn[u];
            kc_cur[u] = kc_nxt[u]; kc_nxt[u] = xA[u]; xA[u] = xB[u];
        }
    }

    // read = M_{L-2}@q per batch, then r2
    #pragma unroll
    for (int u = 0; u < 2; u++)
        rds[u][i] = fmaf(gs2[u], d2[u], fmaf(gs1[u], d1[u], a[u]));
    __syncthreads();

    #pragma unroll
    for (int u = 0; u < 2; u++) {
        float acc = rpb[i];
        #pragma unroll 8
        for (int j = 0; j < 64; j++) acc = fmaf(rds[u][j], rpW[j * HH + i], acc);
        g_r2[(2 * bp + u) * HH + i] = acc;
    }
}

// ---------------------------------------------------------------------------
// Kernel 3: out[b][v] = r2[b] . outW[:, v] + outb[v]
// (round-8 measured-best: 250 blocks x 512 thr, scalar, 2 blocks/SM)
// ---------------------------------------------------------------------------
__global__ void __launch_bounds__(512, 2) k3_out(const float* __restrict__ outW,
                                                 const float* __restrict__ outb,
                                                 float* __restrict__ out) {
    __shared__ float r2s[64 * 64];
    const int tid = threadIdx.x;
    for (int idx = tid; idx < 64 * 64; idx += 512) r2s[idx] = g_r2[idx];
    __syncthreads();

    const int vl = tid & 127;
    const int g  = tid >> 7;           // batch group 0..3
    const int v  = blockIdx.x * 128 + vl;
    const int b0 = g * 16;

    float acc[16];
    #pragma unroll
    for (int bb = 0; bb < 16; bb++) acc[bb] = 0.f;

    #pragma unroll 8
    for (int j = 0; j < 64; j++) {
        float wv = outW[j * VV + v];
        #pragma unroll
        for (int bb = 0; bb < 16; bb++)
            acc[bb] = fmaf(r2s[(b0 + bb) * 64 + j], wv, acc[bb]);
    }
    float ob = outb[v];
    #pragma unroll
    for (int bb = 0; bb < 16; bb++) out[(b0 + bb) * VV + v] = acc[bb] + ob;
}

// ---------------------------------------------------------------------------
extern "C" void kernel_launch(void* const* d_in, const int* in_sizes, int n_in,
                              void* d_out, int out_size) {
    const int*   seq   = (const int*)d_in[0];
    const float* embed = (const float*)d_in[1];
    const float* W1    = (const float*)d_in[2];
    const float* b1    = (const float*)d_in[3];
    const float* W2    = (const float*)d_in[4];
    const float* b2    = (const float*)d_in[5];
    const float* gamma = (const float*)d_in[6];
    const float* beta  = (const float*)d_in[7];
    const float* kpW   = (const float*)d_in[8];
    const float* rpW   = (const float*)d_in[9];
    const float* rpb   = (const float*)d_in[10];
    const float* outW  = (const float*)d_in[11];
    const float* outb  = (const float*)d_in[12];
    float* out = (float*)d_out;

    const int smem1 = (TOK * HPAD + HH * H2 + TOK * H2 + H2 * HH + HH * HH
                       + H2 + 3 * HH) * (int)sizeof(float);
    cudaFuncSetAttribute(k1_frontend, cudaFuncAttributeMaxDynamicSharedMemorySize, smem1);
    cudaFuncSetAttribute(k1_frontend, cudaFuncAttributePreferredSharedMemoryCarveout, 100);

    k1_frontend<<<(BB * LL) / TOK, 512, smem1>>>(seq, embed, W1, b1, W2, b2,
                                                 gamma, beta, kpW);
    k1b_meta<<<(BB * LL) / 8, 256>>>();
    k2_scan<<<BB / 2, 64>>>(rpW, rpb);
    k3_out<<<VV / 128, 512>>>(outW, outb, out);
}

// round 11
// speedup vs baseline: 1.2483x; 1.2483x over previous
#include <cuda_runtime.h>
#include <cuda_bf16.h>
#include <math.h>

#define BB 64
#define LL 1024
#define HH 64
#define H2 128
#define VV 32000
#define TOK 128
#define HPAD 68

// Scratch (device globals; no allocation allowed)
__device__ float  g_kall[BB * LL * HH];   // 16 MB
__device__ float4 g_meta[BB * LL];        // (rinv, 0.16*kk, dot(k_t,k_{t+1}), dot(k_t,k_{t+2}))
__device__ float  g_r2[BB * HH];

// ---------------------------------------------------------------------------
// Kernel 1: per-token front-end (measured-best r2 config: 512 thr, 128 tok)
// ---------------------------------------------------------------------------
__global__ void __launch_bounds__(512) k1_frontend(
        const int* __restrict__ seq, const float* __restrict__ embed,
        const float* __restrict__ W1, const float* __restrict__ b1,
        const float* __restrict__ W2, const float* __restrict__ b2,
        const float* __restrict__ gamma, const float* __restrict__ beta,
        const float* __restrict__ kpW) {
    extern __shared__ float sm[];
    float* h_sm  = sm;
    float* w1_sm = h_sm  + TOK * HPAD;
    float* u_sm  = w1_sm + HH * H2;
    float* w2_sm = u_sm  + TOK * H2;
    float* kp_sm = w2_sm + H2 * HH;
    float* b1s   = kp_sm + HH * HH;
    float* b2s   = b1s + H2;
    float* gsm   = b2s + HH;
    float* bsm   = gsm + HH;

    const int tid  = threadIdx.x;
    const int tok0 = blockIdx.x * TOK;

    for (int idx = tid; idx < HH * H2; idx += 512) w1_sm[idx] = W1[idx];
    for (int idx = tid; idx < H2 * HH; idx += 512) w2_sm[idx] = W2[idx];
    for (int idx = tid; idx < HH * HH; idx += 512) kp_sm[idx] = kpW[idx];
    if (tid < H2) b1s[tid] = b1[tid];
    if (tid < HH) { b2s[tid] = b2[tid]; gsm[tid] = gamma[tid]; bsm[tid] = beta[tid]; }

    #pragma unroll
    for (int k = 0; k < 16; k++) {
        int idx = tid + 512 * k;
        int t = idx >> 6, j = idx & 63;
        int row = seq[tok0 + t];
        h_sm[t * HPAD + j] = embed[row * HH + j];
    }
    __syncthreads();

    const int tt = tid >> 4;
    const int ct = tid & 15;

    // GEMM1
    {
        const int r0 = tt * 4, c0 = ct * 8;
        float acc[4][8];
        #pragma unroll
        for (int r = 0; r < 4; r++)
            #pragma unroll
            for (int c = 0; c < 8; c++) acc[r][c] = 0.f;
        #pragma unroll 2
        for (int j4 = 0; j4 < HH; j4 += 4) {
            float hv[4][4];
            #pragma unroll
            for (int r = 0; r < 4; r++)
                *(float4*)hv[r] = *(const float4*)&h_sm[(r0 + r) * HPAD + j4];
            #pragma unroll
            for (int jj = 0; jj < 4; jj++) {
                float4 wA = *(const float4*)&w1_sm[(j4 + jj) * H2 + c0];
                float4 wB = *(const float4*)&w1_sm[(j4 + jj) * H2 + c0 + 4];
                #pragma unroll
                for (int r = 0; r < 4; r++) {
                    float hvv = hv[r][jj];
                    acc[r][0] = fmaf(hvv, wA.x, acc[r][0]);
                    acc[r][1] = fmaf(hvv, wA.y, acc[r][1]);
                    acc[r][2] = fmaf(hvv, wA.z, acc[r][2]);
                    acc[r][3] = fmaf(hvv, wA.w, acc[r][3]);
                    acc[r][4] = fmaf(hvv, wB.x, acc[r][4]);
                    acc[r][5] = fmaf(hvv, wB.y, acc[r][5]);
                    acc[r][6] = fmaf(hvv, wB.z, acc[r][6]);
                    acc[r][7] = fmaf(hvv, wB.w, acc[r][7]);
                }
            }
        }
        #pragma unroll
        for (int r = 0; r < 4; r++)
            #pragma unroll
            for (int c = 0; c < 8; c++)
                u_sm[(r0 + r) * H2 + c0 + c] = fmaxf(acc[r][c] + b1s[c0 + c], 0.f);
    }
    __syncthreads();

    // GEMM2 + residual
    {
        const int r0 = tt * 4, c0 = ct * 4;
        float acc[4][4];
        #pragma unroll
        for (int r = 0; r < 4; r++)
            #pragma unroll
            for (int c = 0; c < 4; c++) acc[r][c] = 0.f;
        #pragma unroll 2
        for (int j4 = 0; j4 < H2; j4 += 4) {
            float uv[4][4];
            #pragma unroll
            for (int r = 0; r < 4; r++)
                *(float4*)uv[r] = *(const float4*)&u_sm[(r0 + r) * H2 + j4];
            #pragma unroll
            for (int jj = 0; jj < 4; jj++) {
                float4 w = *(const float4*)&w2_sm[(j4 + jj) * HH + c0];
                #pragma unroll
                for (int r = 0; r < 4; r++) {
                    float uvv = uv[r][jj];
                    acc[r][0] = fmaf(uvv, w.x, acc[r][0]);
                    acc[r][1] = fmaf(uvv, w.y, acc[r][1]);
                    acc[r][2] = fmaf(uvv, w.z, acc[r][2]);
                    acc[r][3] = fmaf(uvv, w.w, acc[r][3]);
                }
            }
        }
        #pragma unroll
        for (int r = 0; r < 4; r++)
            #pragma unroll
            for (int c = 0; c < 4; c++)
                h_sm[(r0 + r) * HPAD + c0 + c] += acc[r][c] + b2s[c0 + c];
    }
    __syncthreads();

    // LayerNorm per token
    if (tid < TOK) {
        float s = 0.f, ss = 0.f;
        #pragma unroll 8
        for (int j = 0; j < HH; j++) {
            float x = h_sm[tid * HPAD + j];
            s += x; ss += x * x;
        }
        float mu = s * (1.f / HH);
        float var = ss * (1.f / HH) - mu * mu;
        float rs = rsqrtf(var + 1e-5f);
        #pragma unroll 8
        for (int j = 0; j < HH; j++) {
            float x = h_sm[tid * HPAD + j];
            h_sm[tid * HPAD + j] = (x - mu) * rs * gsm[j] + bsm[j];
        }
    }
    __syncthreads();

    // GEMM3 -> g_kall
    {
        const int r0 = tt * 4, c0 = ct * 4;
        float acc[4][4];
        #pragma unroll
        for (int r = 0; r < 4; r++)
            #pragma unroll
            for (int c = 0; c < 4; c++) acc[r][c] = 0.f;
        #pragma unroll 2
        for (int j4 = 0; j4 < HH; j4 += 4) {
            float hv[4][4];
            #pragma unroll
            for (int r = 0; r < 4; r++)
                *(float4*)hv[r] = *(const float4*)&h_sm[(r0 + r) * HPAD + j4];
            #pragma unroll
            for (int jj = 0; jj < 4; jj++) {
                float4 w = *(const float4*)&kp_sm[(j4 + jj) * HH + c0];
                #pragma unroll
                for (int r = 0; r < 4; r++) {
                    float hvv = hv[r][jj];
                    acc[r][0] = fmaf(hvv, w.x, acc[r][0]);
                    acc[r][1] = fmaf(hvv, w.y, acc[r][1]);
                    acc[r][2] = fmaf(hvv, w.z, acc[r][2]);
                    acc[r][3] = fmaf(hvv, w.w, acc[r][3]);
                }
            }
        }
        #pragma unroll
        for (int r = 0; r < 4; r++)
            #pragma unroll
            for (int c = 0; c < 4; c++)
                g_kall[(tok0 + r0 + r) * HH + c0 + c] = acc[r][c];
    }
}

// ---------------------------------------------------------------------------
// Kernel 1b: per-(b,t) metadata: (rinv, 0.16*kk, dot(k_t,k_{t+1}), dot(k_t,k_{t+2}))
// ---------------------------------------------------------------------------
__global__ void k1b_meta() {
    const int g    = blockIdx.x * 8 + (threadIdx.x >> 5);
    const int lane = threadIdx.x & 31;
    const int b = g >> 10, t = g & 1023;
    if (t >= LL - 1) return;
    const float* kt = g_kall + (b * LL + t) * HH;
    float2 k0 = *(const float2*)&kt[lane * 2];
    float2 k1 = *(const float2*)&kt[HH + lane * 2];
    float2 k2v = make_float2(0.f, 0.f);
    if (t + 2 <= LL - 1) k2v = *(const float2*)&kt[2 * HH + lane * 2];
    float pkk = k0.x * k0.x + k0.y * k0.y;
    float pd1 = k0.x * k1.x + k0.y * k1.y;
    float pd2 = k0.x * k2v.x + k0.y * k2v.y;
    #pragma unroll
    for (int off = 16; off; off >>= 1) {
        pkk += __shfl_xor_sync(0xffffffffu, pkk, off);
        pd1 += __shfl_xor_sync(0xffffffffu, pd1, off);
        pd2 += __shfl_xor_sync(0xffffffffu, pd2, off);
    }
    if (lane == 0) {
        float rinv = 1.0f / fmaxf(sqrtf(pkk), 1e-12f);
        g_meta[b * LL + t] = make_float4(rinv, 0.16f * pkk, pd1, pd2);
    }
}

// ---------------------------------------------------------------------------
// Kernel 2: 4 batches per 256-thread block; batch u on warps {2u, 2u+1},
// synced with NAMED barrier (bar.sync u+1, 64). Warp->SMSP map (wid%4) puts
// two INDEPENDENT batch scans on every SMSP, so one scan's shfl/barrier/LDS
// latency is hidden under the other's FMA stream. Per-batch code identical
// to round-8's 64-thread lag-2 kernel (~90 regs/thread).
// ---------------------------------------------------------------------------
__device__ __forceinline__ void batch_bar(int u) {
    asm volatile("bar.sync %0, 64;" :: "r"(u + 1) : "memory");
}

__global__ void __launch_bounds__(256, 1) k2_scan(const float* __restrict__ rpW,
                                                  const float* __restrict__ rpb) {
    const int tid = threadIdx.x;
    const int u   = tid >> 6;            // batch slot in block (0..3)
    const int i   = tid & 63;            // row within batch
    const int w   = i >> 5;              // warp within batch (0/1)
    const int b   = blockIdx.x * 4 + u;  // global batch

    __shared__ __align__(16) float kbuf[4][8][64];
    __shared__ float wsum[4][2][2];      // [u][parity][warp]
    __shared__ float rds[4][64];

    float M[64];
    #pragma unroll
    for (int j = 0; j < 64; j++) M[j] = 0.f;

    const float*  kb = g_kall + b * LL * HH;
    const float4* mb = g_meta + b * LL;

    // zero kbuf slots (6,7 are read as "k^{t-2}" at t=0,1 with gs2=0)
    #pragma unroll
    for (int sl = 0; sl < 8; sl++) kbuf[u][sl][i] = 0.f;

    float kc_cur = kb[i];            // k^0_i
    float kc_nxt = kb[HH + i];       // k^1_i
    float xA     = kb[2 * HH + i];   // k^2_i
    kbuf[u][0][i] = kc_cur;
    kbuf[u][1][i] = kc_nxt;
    float4 mt = mb[0];
    float a = 0.f;
    float gs1 = 0.f, gs2 = 0.f;      // s_{t-1}, s_{t-2}
    float d1 = 0.f, d2 = 0.f, w_prev = 0.f;
    __syncthreads();                 // one full-block barrier before the loop

    for (int t = 0; t < LL - 1; t++) {
        float xB = (t <= LL - 4) ? kb[(t + 3) * HH + i] : 0.f;
        float4 mtn = mb[t + 1];
        const int p = t & 1;

        // critical-path scalars
        float vpk = fmaf(gs2, d2, fmaf(gs1, d1, a));
        float err = fmaf(-mt.x, vpk, kc_cur);       // k_i - rinv*vpk_i
        float s   = err * mt.x;                     // candidate update scalar
        float perr = err * err;
        #pragma unroll
        for (int off = 16; off; off >>= 1)
            perr += __shfl_xor_sync(0xffffffffu, perr, off);
        if ((i & 31) == 0) wsum[u][p][w] = perr;

        kbuf[u][(t + 2) & 7][i] = xA;               // publish k^{t+2}

        // fused branchless update + matvec (gs2 = 0 when ungated)
        {
            const float* kp = kbuf[u][(t - 2) & 7]; // k^{t-2}
            const float* kn = kbuf[u][(t + 1) & 7]; // k^{t+1}
            float v0 = 0.f, v1 = 0.f, v2 = 0.f, v3 = 0.f;
            #pragma unroll
            for (int j = 0; j < 64; j += 4) {
                float4 kp4 = *(const float4*)&kp[j];
                float4 kn4 = *(const float4*)&kn[j];
                M[j]     = fmaf(gs2, kp4.x, M[j]);     v0 = fmaf(M[j],     kn4.x, v0);
                M[j + 1] = fmaf(gs2, kp4.y, M[j + 1]); v1 = fmaf(M[j + 1], kn4.y, v1);
                M[j + 2] = fmaf(gs2, kp4.z, M[j + 2]); v2 = fmaf(M[j + 2], kn4.z, v2);
                M[j + 3] = fmaf(gs2, kp4.w, M[j + 3]); v3 = fmaf(M[j + 3], kn4.w, v3);
            }
            a = (v0 + v1) + (v2 + v3);              // M_{t-2}@k^{t+1}
        }

        // per-batch named barrier, finalize gate_t, shift pipeline
        batch_bar(u);
        float errsum = wsum[u][p][0] + wsum[u][p][1];
        int gate = errsum >= mt.y;                  // ||err||^2 >= 0.16*||k||^2
        gs2 = gs1;
        gs1 = gate ? s : 0.f;
        d2 = w_prev;            // D(t-1, t+1)
        d1 = mt.z;              // D(t,   t+1)
        w_prev = mt.w;
        mt = mtn;
        kc_cur = kc_nxt; kc_nxt = xA; xA = xB;
    }

    // read = M_{L-2}@q (lag-2 epilogue identical to round 8)
    rds[u][i] = fmaf(gs2, d2, fmaf(gs1, d1, a));
    batch_bar(u);

    // r2[b][i] = read . rpW[:, i] + rpb[i]
    float acc = rpb[i];
    #pragma unroll 8
    for (int j = 0; j < 64; j++) acc = fmaf(rds[u][j], rpW[j * HH + i], acc);
    g_r2[b * HH + i] = acc;
}

// ---------------------------------------------------------------------------
// Kernel 3: out[b][v] = r2[b] . outW[:, v] + outb[v]
// (round-8 measured-best: 250 blocks x 512 thr, scalar, 2 blocks/SM)
// ---------------------------------------------------------------------------
__global__ void __launch_bounds__(512, 2) k3_out(const float* __restrict__ outW,
                                                 const float* __restrict__ outb,
                                                 float* __restrict__ out) {
    __shared__ float r2s[64 * 64];
    const int tid = threadIdx.x;
    for (int idx = tid; idx < 64 * 64; idx += 512) r2s[idx] = g_r2[idx];
    __syncthreads();

    const int vl = tid & 127;
    const int g  = tid >> 7;           // batch group 0..3
    const int v  = blockIdx.x * 128 + vl;
    const int b0 = g * 16;

    float acc[16];
    #pragma unroll
    for (int bb = 0; bb < 16; bb++) acc[bb] = 0.f;

    #pragma unroll 8
    for (int j = 0; j < 64; j++) {
        float wv = outW[j * VV + v];
        #pragma unroll
        for (int bb = 0; bb < 16; bb++)
            acc[bb] = fmaf(r2s[(b0 + bb) * 64 + j], wv, acc[bb]);
    }
    float ob = outb[v];
    #pragma unroll
    for (int bb = 0; bb < 16; bb++) out[(b0 + bb) * VV + v] = acc[bb] + ob;
}

// ---------------------------------------------------------------------------
extern "C" void kernel_launch(void* const* d_in, const int* in_sizes, int n_in,
                              void* d_out, int out_size) {
    const int*   seq   = (const int*)d_in[0];
    const float* embed = (const float*)d_in[1];
    const float* W1    = (const float*)d_in[2];
    const float* b1    = (const float*)d_in[3];
    const float* W2    = (const float*)d_in[4];
    const float* b2    = (const float*)d_in[5];
    const float* gamma = (const float*)d_in[6];
    const float* beta  = (const float*)d_in[7];
    const float* kpW   = (const float*)d_in[8];
    const float* rpW   = (const float*)d_in[9];
    const float* rpb   = (const float*)d_in[10];
    const float* outW  = (const float*)d_in[11];
    const float* outb  = (const float*)d_in[12];
    float* out = (float*)d_out;

    const int smem1 = (TOK * HPAD + HH * H2 + TOK * H2 + H2 * HH + HH * HH
                       + H2 + 3 * HH) * (int)sizeof(float);
    cudaFuncSetAttribute(k1_frontend, cudaFuncAttributeMaxDynamicSharedMemorySize, smem1);
    cudaFuncSetAttribute(k1_frontend, cudaFuncAttributePreferredSharedMemoryCarveout, 100);

    k1_frontend<<<(BB * LL) / TOK, 512, smem1>>>(seq, embed, W1, b1, W2, b2,
                                                 gamma, beta, kpW);
    k1b_meta<<<(BB * LL) / 8, 256>>>();
    k2_scan<<<BB / 4, 256>>>(rpW, rpb);
    k3_out<<<VV / 128, 512>>>(outW, outb, out);
}

// round 12
// speedup vs baseline: 1.6680x; 1.3361x over previous
#include <cuda_runtime.h>
#include <cuda_bf16.h>
#include <math.h>

#define BB 64
#define LL 1024
#define HH 64
#define H2 128
#define VV 32000
#define TOK 64
#define HPAD 68

// Scratch (device globals; no allocation allowed)
__device__ float  g_kall[BB * LL * HH];   // 16 MB
__device__ float4 g_meta[BB * LL];        // (rinv, 0.16*kk, dot(k_t,k_{t+1}), dot(k_t,k_{t+2}))
__device__ float  g_r2[BB * HH];

// ---------------------------------------------------------------------------
// Kernel 1: per-token front-end, 256 threads, 64 tokens/block, ONE reusable
// weight buffer (W1 -> W2 -> kpW) so smem = 84KB -> 2 blocks/SM. Cross-block
// overlap hides barrier/LDS/tail stalls that capped issue at 35%.
// ---------------------------------------------------------------------------
__global__ void __launch_bounds__(256, 2) k1_frontend(
        const int* __restrict__ seq, const float* __restrict__ embed,
        const float* __restrict__ W1, const float* __restrict__ b1,
        const float* __restrict__ W2, const float* __restrict__ b2,
        const float* __restrict__ gamma, const float* __restrict__ beta,
        const float* __restrict__ kpW) {
    extern __shared__ float sm[];
    float* h_sm = sm;                      // TOK * HPAD        (4352)
    float* u_sm = h_sm + TOK * HPAD;       // 64 * 128          (8192)
    float* wbuf = u_sm + TOK * H2;         // 8192 (W1 / W2 / kpW)
    float* b1s  = wbuf + HH * H2;          // 128
    float* b2s  = b1s + H2;                // 64
    float* gsm  = b2s + HH;                // 64
    float* bsm  = gsm + HH;                // 64

    const int tid  = threadIdx.x;
    const int tok0 = blockIdx.x * TOK;

    // ---- phase 1: biases, embed gather, W1 ----
    if (tid < H2) b1s[tid] = b1[tid];
    if (tid < HH) { b2s[tid] = b2[tid]; gsm[tid] = gamma[tid]; bsm[tid] = beta[tid]; }
    {
        const float4* w4 = (const float4*)W1;
        float4* d4 = (float4*)wbuf;
        #pragma unroll
        for (int k = 0; k < 8; k++) d4[tid + 256 * k] = w4[tid + 256 * k];
    }
    #pragma unroll
    for (int k = 0; k < 16; k++) {
        int idx = tid + 256 * k;
        int t = idx >> 6, j = idx & 63;
        int row = seq[tok0 + t];
        h_sm[t * HPAD + j] = embed[row * HH + j];
    }
    __syncthreads();

    const int tt = tid >> 4;   // 0..15
    const int ct = tid & 15;   // 0..15

    // ---- phase 2: GEMM1  u = relu(h @ W1 + b1), 4 tok x 8 col ----
    {
        const int r0 = tt * 4, c0 = ct * 8;
        float acc[4][8];
        #pragma unroll
        for (int r = 0; r < 4; r++)
            #pragma unroll
            for (int c = 0; c < 8; c++) acc[r][c] = 0.f;
        #pragma unroll 2
        for (int j4 = 0; j4 < HH; j4 += 4) {
            float hv[4][4];
            #pragma unroll
            for (int r = 0; r < 4; r++)
                *(float4*)hv[r] = *(const float4*)&h_sm[(r0 + r) * HPAD + j4];
            #pragma unroll
            for (int jj = 0; jj < 4; jj++) {
                float4 wA = *(const float4*)&wbuf[(j4 + jj) * H2 + c0];
                float4 wB = *(const float4*)&wbuf[(j4 + jj) * H2 + c0 + 4];
                #pragma unroll
                for (int r = 0; r < 4; r++) {
                    float hvv = hv[r][jj];
                    acc[r][0] = fmaf(hvv, wA.x, acc[r][0]);
                    acc[r][1] = fmaf(hvv, wA.y, acc[r][1]);
                    acc[r][2] = fmaf(hvv, wA.z, acc[r][2]);
                    acc[r][3] = fmaf(hvv, wA.w, acc[r][3]);
                    acc[r][4] = fmaf(hvv, wB.x, acc[r][4]);
                    acc[r][5] = fmaf(hvv, wB.y, acc[r][5]);
                    acc[r][6] = fmaf(hvv, wB.z, acc[r][6]);
                    acc[r][7] = fmaf(hvv, wB.w, acc[r][7]);
                }
            }
        }
        #pragma unroll
        for (int r = 0; r < 4; r++)
            #pragma unroll
            for (int c = 0; c < 8; c++)
                u_sm[(r0 + r) * H2 + c0 + c] = fmaxf(acc[r][c] + b1s[c0 + c], 0.f);
    }
    __syncthreads();

    // ---- phase 3: load W2 over W1 ----
    {
        const float4* w4 = (const float4*)W2;
        float4* d4 = (float4*)wbuf;
        #pragma unroll
        for (int k = 0; k < 8; k++) d4[tid + 256 * k] = w4[tid + 256 * k];
    }
    __syncthreads();

    // ---- phase 4: GEMM2 + residual  x = u @ W2 + b2 + h (into h_sm) ----
    {
        const int r0 = tt * 4, c0 = ct * 4;
        float acc[4][4];
        #pragma unroll
        for (int r = 0; r < 4; r++)
            #pragma unroll
            for (int c = 0; c < 4; c++) acc[r][c] = 0.f;
        #pragma unroll 2
        for (int j4 = 0; j4 < H2; j4 += 4) {
            float uv[4][4];
            #pragma unroll
            for (int r = 0; r < 4; r++)
                *(float4*)uv[r] = *(const float4*)&u_sm[(r0 + r) * H2 + j4];
            #pragma unroll
            for (int jj = 0; jj < 4; jj++) {
                float4 w = *(const float4*)&wbuf[(j4 + jj) * HH + c0];
                #pragma unroll
                for (int r = 0; r < 4; r++) {
                    float uvv = uv[r][jj];
                    acc[r][0] = fmaf(uvv, w.x, acc[r][0]);
                    acc[r][1] = fmaf(uvv, w.y, acc[r][1]);
                    acc[r][2] = fmaf(uvv, w.z, acc[r][2]);
                    acc[r][3] = fmaf(uvv, w.w, acc[r][3]);
                }
            }
        }
        #pragma unroll
        for (int r = 0; r < 4; r++)
            #pragma unroll
            for (int c = 0; c < 4; c++)
                h_sm[(r0 + r) * HPAD + c0 + c] += acc[r][c] + b2s[c0 + c];
    }
    __syncthreads();

    // ---- phase 5: LN (4 threads/token, quad shfl) + load kpW ----
    {
        const int tq  = tid >> 2;        // token 0..63
        const int sub = tid & 3;         // 16 j's per thread
        const int j0  = sub * 16;
        float s = 0.f, ss = 0.f;
        #pragma unroll 4
        for (int j = j0; j < j0 + 16; j++) {
            float x = h_sm[tq * HPAD + j];
            s += x; ss += x * x;
        }
        s  += __shfl_xor_sync(0xffffffffu, s, 1);
        ss += __shfl_xor_sync(0xffffffffu, ss, 1);
        s  += __shfl_xor_sync(0xffffffffu, s, 2);
        ss += __shfl_xor_sync(0xffffffffu, ss, 2);
        float mu = s * (1.f / HH);
        float var = ss * (1.f / HH) - mu * mu;
        float rs = rsqrtf(var + 1e-5f);
        #pragma unroll 4
        for (int j = j0; j < j0 + 16; j++) {
            float x = h_sm[tq * HPAD + j];
            h_sm[tq * HPAD + j] = (x - mu) * rs * gsm[j] + bsm[j];
        }
        // load kpW into first half of wbuf (W2 fully consumed at phase-4 barrier)
        const float4* w4 = (const float4*)kpW;
        float4* d4 = (float4*)wbuf;
        #pragma unroll
        for (int k = 0; k < 4; k++) d4[tid + 256 * k] = w4[tid + 256 * k];
    }
    __syncthreads();

    // ---- phase 6: GEMM3  k = hn @ kpW -> g_kall ----
    {
        const int r0 = tt * 4, c0 = ct * 4;
        float acc[4][4];
        #pragma unroll
        for (int r = 0; r < 4; r++)
            #pragma unroll
            for (int c = 0; c < 4; c++) acc[r][c] = 0.f;
        #pragma unroll 2
        for (int j4 = 0; j4 < HH; j4 += 4) {
            float hv[4][4];
            #pragma unroll
            for (int r = 0; r < 4; r++)
                *(float4*)hv[r] = *(const float4*)&h_sm[(r0 + r) * HPAD + j4];
            #pragma unroll
            for (int jj = 0; jj < 4; jj++) {
                float4 w = *(const float4*)&wbuf[(j4 + jj) * HH + c0];
                #pragma unroll
                for (int r = 0; r < 4; r++) {
                    float hvv = hv[r][jj];
                    acc[r][0] = fmaf(hvv, w.x, acc[r][0]);
                    acc[r][1] = fmaf(hvv, w.y, acc[r][1]);
                    acc[r][2] = fmaf(hvv, w.z, acc[r][2]);
                    acc[r][3] = fmaf(hvv, w.w, acc[r][3]);
                }
            }
        }
        #pragma unroll
        for (int r = 0; r < 4; r++)
            #pragma unroll
            for (int c = 0; c < 4; c++)
                g_kall[(tok0 + r0 + r) * HH + c0 + c] = acc[r][c];
    }
}

// ---------------------------------------------------------------------------
// Kernel 1b: per-(b,t) metadata: (rinv, 0.16*kk, dot(k_t,k_{t+1}), dot(k_t,k_{t+2}))
// ---------------------------------------------------------------------------
__global__ void k1b_meta() {
    const int g    = blockIdx.x * 8 + (threadIdx.x >> 5);
    const int lane = threadIdx.x & 31;
    const int b = g >> 10, t = g & 1023;
    if (t >= LL - 1) return;
    const float* kt = g_kall + (b * LL + t) * HH;
    float2 k0 = *(const float2*)&kt[lane * 2];
    float2 k1 = *(const float2*)&kt[HH + lane * 2];
    float2 k2v = make_float2(0.f, 0.f);
    if (t + 2 <= LL - 1) k2v = *(const float2*)&kt[2 * HH + lane * 2];
    float pkk = k0.x * k0.x + k0.y * k0.y;
    float pd1 = k0.x * k1.x + k0.y * k1.y;
    float pd2 = k0.x * k2v.x + k0.y * k2v.y;
    #pragma unroll
    for (int off = 16; off; off >>= 1) {
        pkk += __shfl_xor_sync(0xffffffffu, pkk, off);
        pd1 += __shfl_xor_sync(0xffffffffu, pd1, off);
        pd2 += __shfl_xor_sync(0xffffffffu, pd2, off);
    }
    if (lane == 0) {
        float rinv = 1.0f / fmaxf(sqrtf(pkk), 1e-12f);
        g_meta[b * LL + t] = make_float4(rinv, 0.16f * pkk, pd1, pd2);
    }
}

// ---------------------------------------------------------------------------
// Kernel 2: round-8 measured-best 64-thread lag-2 scan (verbatim).
// ---------------------------------------------------------------------------
__global__ void __launch_bounds__(64, 1) k2_scan(const float* __restrict__ rpW,
                                                 const float* __restrict__ rpb) {
    const int b = blockIdx.x;
    const int i = threadIdx.x;
    const int w = i >> 5;
    __shared__ __align__(16) float kbuf[8][64];
    __shared__ float wsum[2][2];
    __shared__ float rds[64];

    float M[64];
    #pragma unroll
    for (int j = 0; j < 64; j++) M[j] = 0.f;

    const float*  kb = g_kall + b * LL * HH;
    const float4* mb = g_meta + b * LL;

    float kc_cur = kb[i];            // k^0_i
    float kc_nxt = kb[HH + i];       // k^1_i
    float xA     = kb[2 * HH + i];   // k^2_i (published at iter 0)
    kbuf[0][i] = kc_cur;
    kbuf[1][i] = kc_nxt;
    float4 mt = mb[0];
    float a = 0.f;
    float gs1 = 0.f, gs2 = 0.f;      // s_{t-1}, s_{t-2} (gated err_i*rinv)
    int   g1 = 0, g2 = 0;            // gate flags (block-uniform)
    float d1 = 0.f, d2 = 0.f, w_prev = 0.f;
    __syncthreads();

    for (int t = 0; t < LL - 1; t++) {
        float xB = (t <= LL - 4) ? kb[(t + 3) * HH + i] : 0.f;
        float4 mtn = mb[t + 1];
        const int p = t & 1;

        // 1. vpk_t = M_{t-1}@k_t via lag-2 base + two corrections (critical chain)
        float vpk = fmaf(gs2, d2, fmaf(gs1, d1, a));
        float err = fmaf(-mt.x, vpk, kc_cur);       // k_i - rinv*vpk_i
        float s   = err * mt.x;                     // candidate update scalar
        float perr = err * err;
        #pragma unroll
        for (int off = 16; off; off >>= 1)
            perr += __shfl_xor_sync(0xffffffffu, perr, off);
        if ((i & 31) == 0) wsum[p][w] = perr;

        kbuf[(t + 2) & 7][i] = xA;                  // publish k^{t+2}

        // 2. apply update s_{t-2}: M_{t-3} -> M_{t-2} (one-iteration-old gate)
        if (g2) {
            const float* kp = kbuf[(t - 2) & 7];
            #pragma unroll
            for (int j = 0; j < 64; j += 4) {
                float4 k4 = *(const float4*)&kp[j];
                M[j]     = fmaf(gs2, k4.x, M[j]);
                M[j + 1] = fmaf(gs2, k4.y, M[j + 1]);
                M[j + 2] = fmaf(gs2, k4.z, M[j + 2]);
                M[j + 3] = fmaf(gs2, k4.w, M[j + 3]);
            }
        }

        // 3. matvec: a = M_{t-2} @ k^{t+1} (independent of gate_{t-1}, gate_t)
        {
            const float* kn = kbuf[(t + 1) & 7];
            float v0 = 0.f, v1 = 0.f, v2 = 0.f, v3 = 0.f;
            #pragma unroll
            for (int j = 0; j < 64; j += 4) {
                float4 k4 = *(const float4*)&kn[j];
                v0 = fmaf(M[j],     k4.x, v0);
                v1 = fmaf(M[j + 1], k4.y, v1);
                v2 = fmaf(M[j + 2], k4.z, v2);
                v3 = fmaf(M[j + 3], k4.w, v3);
            }
            a = (v0 + v1) + (v2 + v3);
        }

        // 4. barrier, finalize gate_t, shift the pipeline
        __syncthreads();
        float errsum = wsum[p][0] + wsum[p][1];
        int gate = errsum >= mt.y;                  // ||err||^2 >= 0.16*||k||^2
        gs2 = gs1;  g2 = g1;
        gs1 = gate ? s : 0.f;  g1 = gate;
        d2 = w_prev;            // D(t-1, t+1) = meta[t-1].w  (lag-2 dot)
        d1 = mt.z;              // D(t,   t+1) = meta[t].z
        w_prev = mt.w;
        mt = mtn;
        kc_cur = kc_nxt; kc_nxt = xA; xA = xB;
    }

    // read = M_{L-2}@q = a + s_{L-3}*D(L-3,L-1) + s_{L-2}*D(L-2,L-1)
    float readv = fmaf(gs2, d2, fmaf(gs1, d1, a));
    rds[i] = readv;
    __syncthreads();

    // r2[b][i] = read . rpW[:, i] + rpb[i]
    float acc = rpb[i];
    #pragma unroll 8
    for (int j = 0; j < 64; j++) acc = fmaf(rds[j], rpW[j * HH + i], acc);
    g_r2[b * HH + i] = acc;
}

// ---------------------------------------------------------------------------
// Kernel 3: out[b][v] = r2[b] . outW[:, v] + outb[v]
// (round-8 measured-best: 250 blocks x 512 thr, scalar, 2 blocks/SM)
// ---------------------------------------------------------------------------
__global__ void __launch_bounds__(512, 2) k3_out(const float* __restrict__ outW,
                                                 const float* __restrict__ outb,
                                                 float* __restrict__ out) {
    __shared__ float r2s[64 * 64];
    const int tid = threadIdx.x;
    for (int idx = tid; idx < 64 * 64; idx += 512) r2s[idx] = g_r2[idx];
    __syncthreads();

    const int vl = tid & 127;
    const int g  = tid >> 7;           // batch group 0..3
    const int v  = blockIdx.x * 128 + vl;
    const int b0 = g * 16;

    float acc[16];
    #pragma unroll
    for (int bb = 0; bb < 16; bb++) acc[bb] = 0.f;

    #pragma unroll 8
    for (int j = 0; j < 64; j++) {
        float wv = outW[j * VV + v];
        #pragma unroll
        for (int bb = 0; bb < 16; bb++)
            acc[bb] = fmaf(r2s[(b0 + bb) * 64 + j], wv, acc[bb]);
    }
    float ob = outb[v];
    #pragma unroll
    for (int bb = 0; bb < 16; bb++) out[(b0 + bb) * VV + v] = acc[bb] + ob;
}

// ---------------------------------------------------------------------------
extern "C" void kernel_launch(void* const* d_in, const int* in_sizes, int n_in,
                              void* d_out, int out_size) {
    const int*   seq   = (const int*)d_in[0];
    const float* embed = (const float*)d_in[1];
    const float* W1    = (const float*)d_in[2];
    const float* b1    = (const float*)d_in[3];
    const float* W2    = (const float*)d_in[4];
    const float* b2    = (const float*)d_in[5];
    const float* gamma = (const float*)d_in[6];
    const float* beta  = (const float*)d_in[7];
    const float* kpW   = (const float*)d_in[8];
    const float* rpW   = (const float*)d_in[9];
    const float* rpb   = (const float*)d_in[10];
    const float* outW  = (const float*)d_in[11];
    const float* outb  = (const float*)d_in[12];
    float* out = (float*)d_out;

    const int smem1 = (TOK * HPAD + TOK * H2 + HH * H2
                       + H2 + 3 * HH) * (int)sizeof(float);
    cudaFuncSetAttribute(k1_frontend, cudaFuncAttributeMaxDynamicSharedMemorySize, smem1);
    cudaFuncSetAttribute(k1_frontend, cudaFuncAttributePreferredSharedMemoryCarveout, 100);

    k1_frontend<<<(BB * LL) / TOK, 256, smem1>>>(seq, embed, W1, b1, W2, b2,
                                                 gamma, beta, kpW);
    k1b_meta<<<(BB * LL) / 8, 256>>>();
    k2_scan<<<BB, 64>>>(rpW, rpb);
    k3_out<<<VV / 128, 512>>>(outW, outb, out);
}

// round 13
// speedup vs baseline: 1.6973x; 1.0176x over previous
#include <cuda_runtime.h>
#include <cuda_bf16.h>
#include <math.h>

#define BB 64
#define LL 1024
#define HH 64
#define H2 128
#define VV 32000
#define TOK 64
#define HPAD 68

// Scratch (device globals; no allocation allowed)
__device__ float  g_kall[BB * LL * HH];   // 16 MB
__device__ float4 g_meta[BB * LL];        // (rinv, 0.16*kk, dot(k_t,k_{t+1}), dot(k_t,k_{t+2}))
__device__ float  g_r2[BB * HH];

// ---------------------------------------------------------------------------
// Kernel 1: per-token front-end, 256 threads, 64 tokens/block, ONE reusable
// weight buffer (W1 -> W2 -> kpW): smem = 84KB -> 2 blocks/SM (round-12 WIN).
// ---------------------------------------------------------------------------
__global__ void __launch_bounds__(256, 2) k1_frontend(
        const int* __restrict__ seq, const float* __restrict__ embed,
        const float* __restrict__ W1, const float* __restrict__ b1,
        const float* __restrict__ W2, const float* __restrict__ b2,
        const float* __restrict__ gamma, const float* __restrict__ beta,
        const float* __restrict__ kpW) {
    extern __shared__ float sm[];
    float* h_sm = sm;                      // TOK * HPAD        (4352)
    float* u_sm = h_sm + TOK * HPAD;       // 64 * 128          (8192)
    float* wbuf = u_sm + TOK * H2;         // 8192 (W1 / W2 / kpW)
    float* b1s  = wbuf + HH * H2;          // 128
    float* b2s  = b1s + H2;                // 64
    float* gsm  = b2s + HH;                // 64
    float* bsm  = gsm + HH;                // 64

    const int tid  = threadIdx.x;
    const int tok0 = blockIdx.x * TOK;

    // ---- phase 1: biases, embed gather, W1 ----
    if (tid < H2) b1s[tid] = b1[tid];
    if (tid < HH) { b2s[tid] = b2[tid]; gsm[tid] = gamma[tid]; bsm[tid] = beta[tid]; }
    {
        const float4* w4 = (const float4*)W1;
        float4* d4 = (float4*)wbuf;
        #pragma unroll
        for (int k = 0; k < 8; k++) d4[tid + 256 * k] = w4[tid + 256 * k];
    }
    #pragma unroll
    for (int k = 0; k < 16; k++) {
        int idx = tid + 256 * k;
        int t = idx >> 6, j = idx & 63;
        int row = seq[tok0 + t];
        h_sm[t * HPAD + j] = embed[row * HH + j];
    }
    __syncthreads();

    const int tt = tid >> 4;   // 0..15
    const int ct = tid & 15;   // 0..15

    // ---- phase 2: GEMM1  u = relu(h @ W1 + b1), 4 tok x 8 col ----
    {
        const int r0 = tt * 4, c0 = ct * 8;
        float acc[4][8];
        #pragma unroll
        for (int r = 0; r < 4; r++)
            #pragma unroll
            for (int c = 0; c < 8; c++) acc[r][c] = 0.f;
        #pragma unroll 2
        for (int j4 = 0; j4 < HH; j4 += 4) {
            float hv[4][4];
            #pragma unroll
            for (int r = 0; r < 4; r++)
                *(float4*)hv[r] = *(const float4*)&h_sm[(r0 + r) * HPAD + j4];
            #pragma unroll
            for (int jj = 0; jj < 4; jj++) {
                float4 wA = *(const float4*)&wbuf[(j4 + jj) * H2 + c0];
                float4 wB = *(const float4*)&wbuf[(j4 + jj) * H2 + c0 + 4];
                #pragma unroll
                for (int r = 0; r < 4; r++) {
                    float hvv = hv[r][jj];
                    acc[r][0] = fmaf(hvv, wA.x, acc[r][0]);
                    acc[r][1] = fmaf(hvv, wA.y, acc[r][1]);
                    acc[r][2] = fmaf(hvv, wA.z, acc[r][2]);
                    acc[r][3] = fmaf(hvv, wA.w, acc[r][3]);
                    acc[r][4] = fmaf(hvv, wB.x, acc[r][4]);
                    acc[r][5] = fmaf(hvv, wB.y, acc[r][5]);
                    acc[r][6] = fmaf(hvv, wB.z, acc[r][6]);
                    acc[r][7] = fmaf(hvv, wB.w, acc[r][7]);
                }
            }
        }
        #pragma unroll
        for (int r = 0; r < 4; r++)
            #pragma unroll
            for (int c = 0; c < 8; c++)
                u_sm[(r0 + r) * H2 + c0 + c] = fmaxf(acc[r][c] + b1s[c0 + c], 0.f);
    }
    __syncthreads();

    // ---- phase 3: load W2 over W1 ----
    {
        const float4* w4 = (const float4*)W2;
        float4* d4 = (float4*)wbuf;
        #pragma unroll
        for (int k = 0; k < 8; k++) d4[tid + 256 * k] = w4[tid + 256 * k];
    }
    __syncthreads();

    // ---- phase 4: GEMM2 + residual  x = u @ W2 + b2 + h (into h_sm) ----
    {
        const int r0 = tt * 4, c0 = ct * 4;
        float acc[4][4];
        #pragma unroll
        for (int r = 0; r < 4; r++)
            #pragma unroll
            for (int c = 0; c < 4; c++) acc[r][c] = 0.f;
        #pragma unroll 2
        for (int j4 = 0; j4 < H2; j4 += 4) {
            float uv[4][4];
            #pragma unroll
            for (int r = 0; r < 4; r++)
                *(float4*)uv[r] = *(const float4*)&u_sm[(r0 + r) * H2 + j4];
            #pragma unroll
            for (int jj = 0; jj < 4; jj++) {
                float4 w = *(const float4*)&wbuf[(j4 + jj) * HH + c0];
                #pragma unroll
                for (int r = 0; r < 4; r++) {
                    float uvv = uv[r][jj];
                    acc[r][0] = fmaf(uvv, w.x, acc[r][0]);
                    acc[r][1] = fmaf(uvv, w.y, acc[r][1]);
                    acc[r][2] = fmaf(uvv, w.z, acc[r][2]);
                    acc[r][3] = fmaf(uvv, w.w, acc[r][3]);
                }
            }
        }
        #pragma unroll
        for (int r = 0; r < 4; r++)
            #pragma unroll
            for (int c = 0; c < 4; c++)
                h_sm[(r0 + r) * HPAD + c0 + c] += acc[r][c] + b2s[c0 + c];
    }
    __syncthreads();

    // ---- phase 5: LN (4 threads/token, quad shfl) + load kpW ----
    {
        const int tq  = tid >> 2;        // token 0..63
        const int sub = tid & 3;         // 16 j's per thread
        const int j0  = sub * 16;
        float s = 0.f, ss = 0.f;
        #pragma unroll 4
        for (int j = j0; j < j0 + 16; j++) {
            float x = h_sm[tq * HPAD + j];
            s += x; ss += x * x;
        }
        s  += __shfl_xor_sync(0xffffffffu, s, 1);
        ss += __shfl_xor_sync(0xffffffffu, ss, 1);
        s  += __shfl_xor_sync(0xffffffffu, s, 2);
        ss += __shfl_xor_sync(0xffffffffu, ss, 2);
        float mu = s * (1.f / HH);
        float var = ss * (1.f / HH) - mu * mu;
        float rs = rsqrtf(var + 1e-5f);
        #pragma unroll 4
        for (int j = j0; j < j0 + 16; j++) {
            float x = h_sm[tq * HPAD + j];
            h_sm[tq * HPAD + j] = (x - mu) * rs * gsm[j] + bsm[j];
        }
        // load kpW into first half of wbuf (W2 fully consumed at phase-4 barrier)
        const float4* w4 = (const float4*)kpW;
        float4* d4 = (float4*)wbuf;
        #pragma unroll
        for (int k = 0; k < 4; k++) d4[tid + 256 * k] = w4[tid + 256 * k];
    }
    __syncthreads();

    // ---- phase 6: GEMM3  k = hn @ kpW -> g_kall ----
    {
        const int r0 = tt * 4, c0 = ct * 4;
        float acc[4][4];
        #pragma unroll
        for (int r = 0; r < 4; r++)
            #pragma unroll
            for (int c = 0; c < 4; c++) acc[r][c] = 0.f;
        #pragma unroll 2
        for (int j4 = 0; j4 < HH; j4 += 4) {
            float hv[4][4];
            #pragma unroll
            for (int r = 0; r < 4; r++)
                *(float4*)hv[r] = *(const float4*)&h_sm[(r0 + r) * HPAD + j4];
            #pragma unroll
            for (int jj = 0; jj < 4; jj++) {
                float4 w = *(const float4*)&wbuf[(j4 + jj) * HH + c0];
                #pragma unroll
                for (int r = 0; r < 4; r++) {
                    float hvv = hv[r][jj];
                    acc[r][0] = fmaf(hvv, w.x, acc[r][0]);
                    acc[r][1] = fmaf(hvv, w.y, acc[r][1]);
                    acc[r][2] = fmaf(hvv, w.z, acc[r][2]);
                    acc[r][3] = fmaf(hvv, w.w, acc[r][3]);
                }
            }
        }
        #pragma unroll
        for (int r = 0; r < 4; r++)
            #pragma unroll
            for (int c = 0; c < 4; c++)
                g_kall[(tok0 + r0 + r) * HH + c0 + c] = acc[r][c];
    }
}

// ---------------------------------------------------------------------------
// Kernel 1b: per-(b,t) metadata: (rinv, 0.16*kk, dot(k_t,k_{t+1}), dot(k_t,k_{t+2}))
// ---------------------------------------------------------------------------
__global__ void k1b_meta() {
    const int g    = blockIdx.x * 8 + (threadIdx.x >> 5);
    const int lane = threadIdx.x & 31;
    const int b = g >> 10, t = g & 1023;
    if (t >= LL - 1) return;
    const float* kt = g_kall + (b * LL + t) * HH;
    float2 k0 = *(const float2*)&kt[lane * 2];
    float2 k1 = *(const float2*)&kt[HH + lane * 2];
    float2 k2v = make_float2(0.f, 0.f);
    if (t + 2 <= LL - 1) k2v = *(const float2*)&kt[2 * HH + lane * 2];
    float pkk = k0.x * k0.x + k0.y * k0.y;
    float pd1 = k0.x * k1.x + k0.y * k1.y;
    float pd2 = k0.x * k2v.x + k0.y * k2v.y;
    #pragma unroll
    for (int off = 16; off; off >>= 1) {
        pkk += __shfl_xor_sync(0xffffffffu, pkk, off);
        pd1 += __shfl_xor_sync(0xffffffffu, pd1, off);
        pd2 += __shfl_xor_sync(0xffffffffu, pd2, off);
    }
    if (lane == 0) {
        float rinv = 1.0f / fmaxf(sqrtf(pkk), 1e-12f);
        g_meta[b * LL + t] = make_float4(rinv, 0.16f * pkk, pd1, pd2);
    }
}

// ---------------------------------------------------------------------------
// Kernel 2: round-8 64-thread lag-2 scan with ONE change: the post-barrier
// gate read uses the in-register own-warp butterfly sum (perr) + a single
// LDS of the other warp's sum, removing one LDS+ADD from the serial chain.
// ---------------------------------------------------------------------------
__global__ void __launch_bounds__(64, 1) k2_scan(const float* __restrict__ rpW,
                                                 const float* __restrict__ rpb) {
    const int b = blockIdx.x;
    const int i = threadIdx.x;
    const int w = i >> 5;
    __shared__ __align__(16) float kbuf[8][64];
    __shared__ float wsum[2][2];
    __shared__ float rds[64];

    float M[64];
    #pragma unroll
    for (int j = 0; j < 64; j++) M[j] = 0.f;

    const float*  kb = g_kall + b * LL * HH;
    const float4* mb = g_meta + b * LL;

    float kc_cur = kb[i];            // k^0_i
    float kc_nxt = kb[HH + i];       // k^1_i
    float xA     = kb[2 * HH + i];   // k^2_i (published at iter 0)
    kbuf[0][i] = kc_cur;
    kbuf[1][i] = kc_nxt;
    float4 mt = mb[0];
    float a = 0.f;
    float gs1 = 0.f, gs2 = 0.f;      // s_{t-1}, s_{t-2} (gated err_i*rinv)
    int   g1 = 0, g2 = 0;            // gate flags (block-uniform)
    float d1 = 0.f, d2 = 0.f, w_prev = 0.f;
    __syncthreads();

    for (int t = 0; t < LL - 1; t++) {
        float xB = (t <= LL - 4) ? kb[(t + 3) * HH + i] : 0.f;
        float4 mtn = mb[t + 1];
        const int p = t & 1;

        // 1. vpk_t = M_{t-1}@k_t via lag-2 base + two corrections (critical chain)
        float vpk = fmaf(gs2, d2, fmaf(gs1, d1, a));
        float err = fmaf(-mt.x, vpk, kc_cur);       // k_i - rinv*vpk_i
        float s   = err * mt.x;                     // candidate update scalar
        float perr = err * err;
        #pragma unroll
        for (int off = 16; off; off >>= 1)
            perr += __shfl_xor_sync(0xffffffffu, perr, off);
        if ((i & 31) == 0) wsum[p][w] = perr;       // publish own-warp sum

        kbuf[(t + 2) & 7][i] = xA;                  // publish k^{t+2}

        // 2. apply update s_{t-2}: M_{t-3} -> M_{t-2} (one-iteration-old gate)
        if (g2) {
            const float* kp = kbuf[(t - 2) & 7];
            #pragma unroll
            for (int j = 0; j < 64; j += 4) {
                float4 k4 = *(const float4*)&kp[j];
                M[j]     = fmaf(gs2, k4.x, M[j]);
                M[j + 1] = fmaf(gs2, k4.y, M[j + 1]);
                M[j + 2] = fmaf(gs2, k4.z, M[j + 2]);
                M[j + 3] = fmaf(gs2, k4.w, M[j + 3]);
            }
        }

        // 3. matvec: a = M_{t-2} @ k^{t+1} (independent of gate_{t-1}, gate_t)
        {
            const float* kn = kbuf[(t + 1) & 7];
            float v0 = 0.f, v1 = 0.f, v2 = 0.f, v3 = 0.f;
            #pragma unroll
            for (int j = 0; j < 64; j += 4) {
                float4 k4 = *(const float4*)&kn[j];
                v0 = fmaf(M[j],     k4.x, v0);
                v1 = fmaf(M[j + 1], k4.y, v1);
                v2 = fmaf(M[j + 2], k4.z, v2);
                v3 = fmaf(M[j + 3], k4.w, v3);
            }
            a = (v0 + v1) + (v2 + v3);
        }

        // 4. barrier, finalize gate_t (own sum in register + ONE LDS)
        __syncthreads();
        float errsum = perr + wsum[p][w ^ 1];
        int gate = errsum >= mt.y;                  // ||err||^2 >= 0.16*||k||^2
        gs2 = gs1;  g2 = g1;
        gs1 = gate ? s : 0.f;  g1 = gate;
        d2 = w_prev;            // D(t-1, t+1) = meta[t-1].w  (lag-2 dot)
        d1 = mt.z;              // D(t,   t+1) = meta[t].z
        w_prev = mt.w;
        mt = mtn;
        kc_cur = kc_nxt; kc_nxt = xA; xA = xB;
    }

    // read = M_{L-2}@q = a + s_{L-3}*D(L-3,L-1) + s_{L-2}*D(L-2,L-1)
    float readv = fmaf(gs2, d2, fmaf(gs1, d1, a));
    rds[i] = readv;
    __syncthreads();

    // r2[b][i] = read . rpW[:, i] + rpb[i]
    float acc = rpb[i];
    #pragma unroll 8
    for (int j = 0; j < 64; j++) acc = fmaf(rds[j], rpW[j * HH + i], acc);
    g_r2[b * HH + i] = acc;
}

// ---------------------------------------------------------------------------
// Kernel 3: out[b][v] = r2[b] . outW[:, v] + outb[v]
// 250 blocks x 512 thr: 64 float2-lanes (128 v per block) x 8 groups x 8
// batches. Per j: 1 LDG.64 + 8 LDS + 16 FMA (was 1+16+16).
// ---------------------------------------------------------------------------
__global__ void __launch_bounds__(512, 2) k3_out(const float* __restrict__ outW,
                                                 const float* __restrict__ outb,
                                                 float* __restrict__ out) {
    __shared__ float r2s[64 * 64];
    const int tid = threadIdx.x;
    for (int idx = tid; idx < 64 * 64; idx += 512) r2s[idx] = g_r2[idx];
    __syncthreads();

    const int vl = tid & 63;           // float2 lane 0..63
    const int g  = tid >> 6;           // batch group 0..7
    const int v2 = blockIdx.x * 64 + vl;    // of 16000 float2 columns
    const int b0 = g * 8;

    const float2* outW2 = (const float2*)outW;
    float2 acc[8];
    #pragma unroll
    for (int bb = 0; bb < 8; bb++) acc[bb] = make_float2(0.f, 0.f);

    #pragma unroll 8
    for (int j = 0; j < 64; j++) {
        float2 wv = outW2[j * (VV / 2) + v2];
        #pragma unroll
        for (int bb = 0; bb < 8; bb++) {
            float r = r2s[(b0 + bb) * 64 + j];
            acc[bb].x = fmaf(r, wv.x, acc[bb].x);
            acc[bb].y = fmaf(r, wv.y, acc[bb].y);
        }
    }
    float2 ob = ((const float2*)outb)[v2];
    float2* out2 = (float2*)out;
    #pragma unroll
    for (int bb = 0; bb < 8; bb++) {
        float2 r = acc[bb];
        r.x += ob.x; r.y += ob.y;
        out2[(b0 + bb) * (VV / 2) + v2] = r;
    }
}

// ---------------------------------------------------------------------------
extern "C" void kernel_launch(void* const* d_in, const int* in_sizes, int n_in,
                              void* d_out, int out_size) {
    const int*   seq   = (const int*)d_in[0];
    const float* embed = (const float*)d_in[1];
    const float* W1    = (const float*)d_in[2];
    const float* b1    = (const float*)d_in[3];
    const float* W2    = (const float*)d_in[4];
    const float* b2    = (const float*)d_in[5];
    const float* gamma = (const float*)d_in[6];
    const float* beta  = (const float*)d_in[7];
    const float* kpW   = (const float*)d_in[8];
    const float* rpW   = (const float*)d_in[9];
    const float* rpb   = (const float*)d_in[10];
    const float* outW  = (const float*)d_in[11];
    const float* outb  = (const float*)d_in[12];
    float* out = (float*)d_out;

    const int smem1 = (TOK * HPAD + TOK * H2 + HH * H2
                       + H2 + 3 * HH) * (int)sizeof(float);
    cudaFuncSetAttribute(k1_frontend, cudaFuncAttributeMaxDynamicSharedMemorySize, smem1);
    cudaFuncSetAttribute(k1_frontend, cudaFuncAttributePreferredSharedMemoryCarveout, 100);

    k1_frontend<<<(BB * LL) / TOK, 256, smem1>>>(seq, embed, W1, b1, W2, b2,
                                                 gamma, beta, kpW);
    k1b_meta<<<(BB * LL) / 8, 256>>>();
    k2_scan<<<BB, 64>>>(rpW, rpb);
    k3_out<<<VV / 128, 512>>>(outW, outb, out);
}